// round 12
// baseline (speedup 1.0000x reference)
#include <cuda_runtime.h>
#include <cstdint>
#include <math.h>

// Problem dims
#define BATCH 256
#define SEQ   512
#define INDIM 32
#define HID   256
#define G3    768      // 3*HID
#define PREDL 96

// ---------------- scratch (static device memory; no allocation) ----------------
__device__ float g_xp0[(size_t)BATCH * SEQ * G3];   // x @ W_ih_l0^T + b_ih_l0
__device__ float g_xp1[(size_t)BATCH * SEQ * G3];   // h1 @ W_ih_l1^T + b_ih_l1
__device__ float g_h1 [(size_t)BATCH * SEQ * HID];  // layer-0 hidden states
__device__ float g_hfin[BATCH * HID];               // final hidden of layer 1

// ---------------- f32x2 packed helpers ----------------
__device__ __forceinline__ unsigned long long pack2(float lo, float hi) {
    unsigned long long r;
    asm("mov.b64 %0, {%1,%2};" : "=l"(r) : "f"(lo), "f"(hi));
    return r;
}
__device__ __forceinline__ void unpack2(unsigned long long v, float& lo, float& hi) {
    asm("mov.b64 {%0,%1}, %2;" : "=f"(lo), "=f"(hi) : "l"(v));
}
__device__ __forceinline__ unsigned long long ffma2(unsigned long long a,
                                                    unsigned long long b,
                                                    unsigned long long c) {
    unsigned long long d;
    asm("fma.rn.f32x2 %0, %1, %2, %3;" : "=l"(d) : "l"(a), "l"(b), "l"(c));
    return d;
}

__device__ __forceinline__ float fsig(float x) {
    return __fdividef(1.f, 1.f + __expf(-x));
}
__device__ __forceinline__ float ftanh_(float x) {
    return 1.f - __fdividef(2.f, __expf(2.f * x) + 1.f);
}

// =======================================================================
// GEMM v2:  C[M,N] = A[M,K] @ W[N,K]^T + bias[N]   (fp32, FFMA2)
// 128x64 block tile, 8x4 per thread (m-pair FFMA2), 256 threads,
// double-buffered k=16 tiles, one __syncthreads per tile.   (unchanged)
// =======================================================================
__global__ __launch_bounds__(256) void gemm_bias(
        const float* __restrict__ A, const float* __restrict__ W,
        const float* __restrict__ bias, float* __restrict__ C,
        int M, int N, int K) {
    __shared__ float As[2][16][132];
    __shared__ float Bs[2][16][68];
    const int tid = threadIdx.x;
    const int n0 = blockIdx.x * 64;
    const int m0 = blockIdx.y * 128;
    const int tx = tid & 15, ty = tid >> 4;

    const int mA  = tid >> 1;
    const int kcA = (tid & 1) * 2;
    const int nB  = tid >> 2;
    const int kcB = tid & 3;

    const float4* Arow = (const float4*)(A + (size_t)(m0 + mA) * K);
    const float4* Brow = (const float4*)(W + (size_t)(n0 + nB) * K);

    float4 va0 = Arow[kcA];
    float4 va1 = Arow[kcA + 1];
    float4 vb  = Brow[kcB];

    As[0][kcA * 4 + 0][mA] = va0.x; As[0][kcA * 4 + 1][mA] = va0.y;
    As[0][kcA * 4 + 2][mA] = va0.z; As[0][kcA * 4 + 3][mA] = va0.w;
    As[0][kcA * 4 + 4][mA] = va1.x; As[0][kcA * 4 + 5][mA] = va1.y;
    As[0][kcA * 4 + 6][mA] = va1.z; As[0][kcA * 4 + 7][mA] = va1.w;
    Bs[0][kcB * 4 + 0][nB] = vb.x;  Bs[0][kcB * 4 + 1][nB] = vb.y;
    Bs[0][kcB * 4 + 2][nB] = vb.z;  Bs[0][kcB * 4 + 3][nB] = vb.w;
    __syncthreads();

    unsigned long long acc[4][4];
#pragma unroll
    for (int p = 0; p < 4; p++)
#pragma unroll
        for (int n = 0; n < 4; n++) acc[p][n] = 0ull;

    const int ntiles = K >> 4;
    for (int kt = 0; kt < ntiles; kt++) {
        const int s = kt & 1;
        if (kt + 1 < ntiles) {
            va0 = Arow[(kt + 1) * 4 + kcA];
            va1 = Arow[(kt + 1) * 4 + kcA + 1];
            vb  = Brow[(kt + 1) * 4 + kcB];
        }
#pragma unroll
        for (int kk = 0; kk < 16; kk++) {
            const float* ar = &As[s][kk][ty * 8];
            ulonglong2 aA = *(const ulonglong2*)ar;
            ulonglong2 aB = *(const ulonglong2*)(ar + 4);
            float4 b4 = *(const float4*)&Bs[s][kk][tx * 4];
            unsigned long long bp0 = pack2(b4.x, b4.x);
            unsigned long long bp1 = pack2(b4.y, b4.y);
            unsigned long long bp2 = pack2(b4.z, b4.z);
            unsigned long long bp3 = pack2(b4.w, b4.w);
            acc[0][0] = ffma2(aA.x, bp0, acc[0][0]); acc[0][1] = ffma2(aA.x, bp1, acc[0][1]);
            acc[0][2] = ffma2(aA.x, bp2, acc[0][2]); acc[0][3] = ffma2(aA.x, bp3, acc[0][3]);
            acc[1][0] = ffma2(aA.y, bp0, acc[1][0]); acc[1][1] = ffma2(aA.y, bp1, acc[1][1]);
            acc[1][2] = ffma2(aA.y, bp2, acc[1][2]); acc[1][3] = ffma2(aA.y, bp3, acc[1][3]);
            acc[2][0] = ffma2(aB.x, bp0, acc[2][0]); acc[2][1] = ffma2(aB.x, bp1, acc[2][1]);
            acc[2][2] = ffma2(aB.x, bp2, acc[2][2]); acc[2][3] = ffma2(aB.x, bp3, acc[2][3]);
            acc[3][0] = ffma2(aB.y, bp0, acc[3][0]); acc[3][1] = ffma2(aB.y, bp1, acc[3][1]);
            acc[3][2] = ffma2(aB.y, bp2, acc[3][2]); acc[3][3] = ffma2(aB.y, bp3, acc[3][3]);
        }
        if (kt + 1 < ntiles) {
            const int s1 = s ^ 1;
            As[s1][kcA * 4 + 0][mA] = va0.x; As[s1][kcA * 4 + 1][mA] = va0.y;
            As[s1][kcA * 4 + 2][mA] = va0.z; As[s1][kcA * 4 + 3][mA] = va0.w;
            As[s1][kcA * 4 + 4][mA] = va1.x; As[s1][kcA * 4 + 5][mA] = va1.y;
            As[s1][kcA * 4 + 6][mA] = va1.z; As[s1][kcA * 4 + 7][mA] = va1.w;
            Bs[s1][kcB * 4 + 0][nB] = vb.x;  Bs[s1][kcB * 4 + 1][nB] = vb.y;
            Bs[s1][kcB * 4 + 2][nB] = vb.z;  Bs[s1][kcB * 4 + 3][nB] = vb.w;
        }
        __syncthreads();
    }

    float4 bb = *(const float4*)(bias + n0 + tx * 4);
#pragma unroll
    for (int p = 0; p < 4; p++) {
        float l0, h0, l1, h1, l2, h2, l3, h3;
        unpack2(acc[p][0], l0, h0);
        unpack2(acc[p][1], l1, h1);
        unpack2(acc[p][2], l2, h2);
        unpack2(acc[p][3], l3, h3);
        int m = m0 + ty * 8 + p * 2;
        float4 r0 = make_float4(l0 + bb.x, l1 + bb.y, l2 + bb.z, l3 + bb.w);
        float4 r1 = make_float4(h0 + bb.x, h1 + bb.y, h2 + bb.z, h3 + bb.w);
        *(float4*)(C + (size_t)m * N + n0 + tx * 4) = r0;
        *(float4*)(C + (size_t)(m + 1) * N + n0 + tx * 4) = r1;
    }
}

// =======================================================================
// GRU recurrence v5: two-group software pipeline.
// 8 batches/cluster split into group A (rows 0-3) and B (rows 4-7) —
// independent recurrences. Per step: waitA, computeA, pushA/arriveA,
// waitB, computeB, pushB/arriveB. Each group's exchange+barrier latency
// is hidden under the other group's compute. 4 mbarriers (group x parity),
// 32 arrivals each (8 warps x 4 CTAs). v4 WAR proof applies per group.
// =======================================================================
#define WBLK  13064
#define WT_WORDS (4 * WBLK)             // 52256
#define HSTR  276
#define HBUF_WORDS (8 * HSTR)           // 2208 per parity buffer (8 batch rows)
#define MBAR_OFF_WORDS (WT_WORDS + 2 * HBUF_WORDS)
#define GRU_SMEM_FLOATS (MBAR_OFF_WORDS + 8)   // 4 b64 mbarriers
#define GRU_SMEM_BYTES  (GRU_SMEM_FLOATS * 4)

__device__ __forceinline__ uint32_t smem_u32(const void* p) {
    return (uint32_t)__cvta_generic_to_shared(p);
}

// acquire-cluster parity wait on a local mbarrier
#define MBAR_WAIT_CLU(mbar, ph) do {                                          \
    uint32_t _m = (mbar), _p = (ph), _d;                                      \
    asm volatile("{\n\t.reg .pred p;\n\t"                                     \
        "mbarrier.try_wait.parity.acquire.cluster.shared::cta.b64 p, [%1], %2, 0x989680;\n\t" \
        "selp.b32 %0, 1, 0, p;\n\t}"                                          \
        : "=r"(_d) : "r"(_m), "r"(_p) : "memory");                            \
    if (!_d) {                                                                \
        asm volatile("{\n\t.reg .pred P1;\n\t"                                \
            "WL_%=:\n\t"                                                      \
            "mbarrier.try_wait.parity.acquire.cluster.shared::cta.b64 P1, [%0], %1, 0x989680;\n\t" \
            "@P1 bra.uni WD_%=;\n\t"                                          \
            "bra.uni WL_%=;\n\t"                                              \
            "WD_%=:\n\t}"                                                     \
            :: "r"(_m), "r"(_p) : "memory");                                  \
    }                                                                         \
} while (0)

template <bool WRITE_ALL>
__global__ __launch_bounds__(256, 1) __cluster_dims__(4, 1, 1)
void gru_layer(const float* __restrict__ xp, const float* __restrict__ W_hh,
               const float* __restrict__ b_hh, float* __restrict__ hout) {
    extern __shared__ float smem[];
    float* Wt   = smem;                 // WT_WORDS
    float* hbuf = smem + WT_WORDS;      // 2 parity buffers x 8 batch rows x HSTR

    const int tid = threadIdx.x;
    const int kq  = tid & 3;
    const int u   = tid >> 2;           // 0..63
    uint32_t rank;
    asm("mov.u32 %0, %%cluster_ctarank;" : "=r"(rank));
    const int gu  = (int)rank * 64 + u;
    const int b0  = (blockIdx.x >> 2) * 8;

    const uint32_t mbar_base = smem_u32(smem + MBAR_OFF_WORDS);
    // mbar layout: [A,parity0][A,parity1][B,parity0][B,parity1], 8B each

    // Load W_hh slice into kq-blocked layout (coalesced over k).
    for (int idx = tid; idx < 192 * 256; idx += 256) {
        int row = idx >> 8, k = idx & 255;
        int grow = ((row >> 6) << 8) + (int)rank * 64 + (row & 63);
        Wt[(k >> 6) * WBLK + row * 68 + (k & 63)] = W_hh[grow * 256 + k];
    }
    for (int i = tid; i < 2 * HBUF_WORDS; i += 256) hbuf[i] = 0.f;
    if (tid == 0) {
#pragma unroll
        for (int m = 0; m < 4; m++)
            asm volatile("mbarrier.init.shared.b64 [%0], %1;"
                         :: "r"(mbar_base + m * 8), "r"(32u) : "memory");
    }

    const float bh0 = b_hh[gu], bh1 = b_hh[256 + gu], bh2 = b_hh[512 + gu];

    // this lane finalizes batch A: b0+kq (row kq), batch B: b0+4+kq (row 4+kq)
    const float* pxa = xp + ((size_t)(b0 + kq) * SEQ) * G3 + gu;
    const float* pxb = xp + ((size_t)(b0 + 4 + kq) * SEQ) * G3 + gu;
    const int hoffA = kq * HSTR + (int)rank * 68 + u;   // row kq, unit gu

    // Precompute remote push addresses (loop-invariant mapa):
    // rp[parity][rank] -> word hoffA of that parity buffer in CTA 'rank'.
    // B row is +4*HSTR*4 = 4416 bytes from A row (immediate offset).
    uint32_t rp0[4], rp1[4];
    {
        uint32_t l0 = smem_u32(hbuf + hoffA);
        uint32_t l1 = smem_u32(hbuf + HBUF_WORDS + hoffA);
#pragma unroll
        for (int p = 0; p < 4; p++) {
            asm volatile("mapa.shared::cluster.u32 %0, %1, %2;"
                         : "=r"(rp0[p]) : "r"(l0), "r"(p));
            asm volatile("mapa.shared::cluster.u32 %0, %1, %2;"
                         : "=r"(rp1[p]) : "r"(l1), "r"(p));
        }
    }

    // init (W, hbuf, mbarriers) visible cluster-wide before any push/arrive
    asm volatile("barrier.cluster.arrive.aligned;" ::: "memory");
    asm volatile("barrier.cluster.wait.aligned;" ::: "memory");

    const bool q1 = (kq & 1), q2 = (kq & 2);
    const float* wbase = Wt + kq * WBLK + u * 68;

    for (int t = 0; t < SEQ; t++) {
        const int cur = t & 1, nxt = cur ^ 1;
        const uint32_t wait_mb_off = (uint32_t)(((t - 1) & 1) * 8);
        const uint32_t wait_ph     = (uint32_t)(((t - 1) >> 1) & 1);
        const uint32_t arr_mb_off  = (uint32_t)((t & 1) * 8);

        // prefetch input projections for both groups
        float xa_r = pxa[0], xa_z = pxa[256], xa_n = pxa[512];
        float xb_r = pxb[0], xb_z = pxb[256], xb_n = pxb[512];
        pxa += G3; pxb += G3;

        // ================= group A =================
        if (t > 0) MBAR_WAIT_CLU(mbar_base + wait_mb_off, wait_ph);
        {
            unsigned long long acc[3][4];
#pragma unroll
            for (int g = 0; g < 3; g++)
#pragma unroll
                for (int j = 0; j < 4; j++) acc[g][j] = 0ull;

            const float* hb = hbuf + cur * HBUF_WORDS + kq * 68;  // rows 0-3
#pragma unroll 4
            for (int c = 0; c < 16; c++) {
                const int kl = c * 4;
                ulonglong2 w0 = *(const ulonglong2*)(wbase + kl);
                ulonglong2 w1 = *(const ulonglong2*)(wbase + 4352 + kl);
                ulonglong2 w2 = *(const ulonglong2*)(wbase + 8704 + kl);
#pragma unroll
                for (int j = 0; j < 4; j++) {
                    ulonglong2 h2 = *(const ulonglong2*)(hb + j * HSTR + kl);
                    acc[0][j] = ffma2(w0.x, h2.x, acc[0][j]);
                    acc[0][j] = ffma2(w0.y, h2.y, acc[0][j]);
                    acc[1][j] = ffma2(w1.x, h2.x, acc[1][j]);
                    acc[1][j] = ffma2(w1.y, h2.y, acc[1][j]);
                    acc[2][j] = ffma2(w2.x, h2.x, acc[2][j]);
                    acc[2][j] = ffma2(w2.y, h2.y, acc[2][j]);
                }
            }
            float hp = hbuf[cur * HBUF_WORDS + hoffA];

            float v[3][4];
#pragma unroll
            for (int g = 0; g < 3; g++)
#pragma unroll
                for (int j = 0; j < 4; j++) {
                    float lo, hi;
                    unpack2(acc[g][j], lo, hi);
                    v[g][j] = lo + hi;
                }
            float s[3];
#pragma unroll
            for (int g = 0; g < 3; g++) {
                float send0 = q2 ? v[g][0] : v[g][2];
                float keep0 = q2 ? v[g][2] : v[g][0];
                float w20 = keep0 + __shfl_xor_sync(0xFFFFFFFFu, send0, 2);
                float send1 = q2 ? v[g][1] : v[g][3];
                float keep1 = q2 ? v[g][3] : v[g][1];
                float w21 = keep1 + __shfl_xor_sync(0xFFFFFFFFu, send1, 2);
                float send = q1 ? w20 : w21;
                float keep = q1 ? w21 : w20;
                s[g] = keep + __shfl_xor_sync(0xFFFFFFFFu, send, 1);
            }

            float r = fsig(xa_r + s[0] + bh0);
            float z = fsig(xa_z + s[1] + bh1);
            float n = ftanh_(xa_n + r * (s[2] + bh2));
            float hn = (1.f - z) * n + z * hp;

#pragma unroll
            for (int p = 0; p < 4; p++) {
                uint32_t ra = nxt ? rp1[p] : rp0[p];
                asm volatile("st.shared::cluster.f32 [%0], %1;"
                             :: "r"(ra), "f"(hn) : "memory");
            }
            __syncwarp();
            if ((tid & 31) == 0) {
                const uint32_t mb = mbar_base + arr_mb_off;     // group A
#pragma unroll
                for (int p = 0; p < 4; p++) {
                    uint32_t ra;
                    asm volatile("mapa.shared::cluster.u32 %0, %1, %2;"
                                 : "=r"(ra) : "r"(mb), "r"(p));
                    asm volatile("mbarrier.arrive.release.cluster.shared::cluster.b64 _, [%0];"
                                 :: "r"(ra) : "memory");
                }
            }
            if (WRITE_ALL)
                hout[((size_t)(b0 + kq) * SEQ + t) * HID + gu] = hn;
            else if (t == SEQ - 1)
                hout[(b0 + kq) * HID + gu] = hn;
        }

        // ================= group B =================
        if (t > 0) MBAR_WAIT_CLU(mbar_base + 16 + wait_mb_off, wait_ph);
        {
            unsigned long long acc[3][4];
#pragma unroll
            for (int g = 0; g < 3; g++)
#pragma unroll
                for (int j = 0; j < 4; j++) acc[g][j] = 0ull;

            const float* hb = hbuf + cur * HBUF_WORDS + 4 * HSTR + kq * 68;  // rows 4-7
#pragma unroll 4
            for (int c = 0; c < 16; c++) {
                const int kl = c * 4;
                ulonglong2 w0 = *(const ulonglong2*)(wbase + kl);
                ulonglong2 w1 = *(const ulonglong2*)(wbase + 4352 + kl);
                ulonglong2 w2 = *(const ulonglong2*)(wbase + 8704 + kl);
#pragma unroll
                for (int j = 0; j < 4; j++) {
                    ulonglong2 h2 = *(const ulonglong2*)(hb + j * HSTR + kl);
                    acc[0][j] = ffma2(w0.x, h2.x, acc[0][j]);
                    acc[0][j] = ffma2(w0.y, h2.y, acc[0][j]);
                    acc[1][j] = ffma2(w1.x, h2.x, acc[1][j]);
                    acc[1][j] = ffma2(w1.y, h2.y, acc[1][j]);
                    acc[2][j] = ffma2(w2.x, h2.x, acc[2][j]);
                    acc[2][j] = ffma2(w2.y, h2.y, acc[2][j]);
                }
            }
            float hp = hbuf[cur * HBUF_WORDS + 4 * HSTR + hoffA];

            float v[3][4];
#pragma unroll
            for (int g = 0; g < 3; g++)
#pragma unroll
                for (int j = 0; j < 4; j++) {
                    float lo, hi;
                    unpack2(acc[g][j], lo, hi);
                    v[g][j] = lo + hi;
                }
            float s[3];
#pragma unroll
            for (int g = 0; g < 3; g++) {
                float send0 = q2 ? v[g][0] : v[g][2];
                float keep0 = q2 ? v[g][2] : v[g][0];
                float w20 = keep0 + __shfl_xor_sync(0xFFFFFFFFu, send0, 2);
                float send1 = q2 ? v[g][1] : v[g][3];
                float keep1 = q2 ? v[g][3] : v[g][1];
                float w21 = keep1 + __shfl_xor_sync(0xFFFFFFFFu, send1, 2);
                float send = q1 ? w20 : w21;
                float keep = q1 ? w21 : w20;
                s[g] = keep + __shfl_xor_sync(0xFFFFFFFFu, send, 1);
            }

            float r = fsig(xb_r + s[0] + bh0);
            float z = fsig(xb_z + s[1] + bh1);
            float n = ftanh_(xb_n + r * (s[2] + bh2));
            float hn = (1.f - z) * n + z * hp;

#pragma unroll
            for (int p = 0; p < 4; p++) {
                uint32_t ra = nxt ? rp1[p] : rp0[p];
                asm volatile("st.shared::cluster.f32 [%0+4416], %1;"   // +4*HSTR*4 B
                             :: "r"(ra), "f"(hn) : "memory");
            }
            __syncwarp();
            if ((tid & 31) == 0) {
                const uint32_t mb = mbar_base + 16 + arr_mb_off;    // group B
#pragma unroll
                for (int p = 0; p < 4; p++) {
                    uint32_t ra;
                    asm volatile("mapa.shared::cluster.u32 %0, %1, %2;"
                                 : "=r"(ra) : "r"(mb), "r"(p));
                    asm volatile("mbarrier.arrive.release.cluster.shared::cluster.b64 _, [%0];"
                                 :: "r"(ra) : "memory");
                }
            }
            if (WRITE_ALL)
                hout[((size_t)(b0 + 4 + kq) * SEQ + t) * HID + gu] = hn;
            else if (t == SEQ - 1)
                hout[(b0 + 4 + kq) * HID + gu] = hn;
        }
    }

    // Drain in-flight remote stores/arrives before any CTA's SMEM is freed.
    asm volatile("barrier.cluster.arrive.aligned;" ::: "memory");
    asm volatile("barrier.cluster.wait.aligned;" ::: "memory");
}

// =======================================================================
// Final projection + 96-step linear state-space decode. 1 block per batch row.
// =======================================================================
__global__ void final_kernel(const float* __restrict__ hfin, const float* __restrict__ Wp,
                             const float* __restrict__ bp, const float* __restrict__ Cm,
                             const float* __restrict__ rld, const float* __restrict__ rtd,
                             const float* __restrict__ rg, const float* __restrict__ om,
                             float* __restrict__ out) {
    __shared__ float hs[256];
    __shared__ float ss[128];
    const int b = blockIdx.x, tid = threadIdx.x;  // 128 threads
    hs[tid]       = hfin[b * 256 + tid];
    hs[tid + 128] = hfin[b * 256 + 128 + tid];
    __syncthreads();

    float acc = bp[tid];
    const float* w = Wp + tid * 256;
#pragma unroll 8
    for (int k = 0; k < 256; k++) acc += w[k] * hs[k];
    ss[tid] = acc;
    __syncthreads();

    if (tid < 32) {
        const int d = tid;
        float s0 = ss[d * 4 + 0], s1 = ss[d * 4 + 1], s2 = ss[d * 4 + 2], s3 = ss[d * 4 + 3];
        const float al = 1.f / (1.f + expf(-rld[d])) * 0.15f + 0.85f;
        const float at = 1.f / (1.f + expf(-rtd[d])) * 0.25f + 0.70f;
        const float g  = 1.f / (1.f + expf(-rg[d]))  * 0.20f + 0.80f;
        const float c = cosf(om[d]), sn = sinf(om[d]);
        const float r00 = g * c, r01 = -g * sn, r10 = g * sn, r11 = g * c;
        const float C0 = Cm[d * 4 + 0], C1 = Cm[d * 4 + 1];
        const float C2 = Cm[d * 4 + 2], C3 = Cm[d * 4 + 3];
        float* ob = out + (size_t)b * PREDL * 32 + d;
#pragma unroll 4
        for (int t = 0; t < PREDL; t++) {
            float n0 = s0 * al;
            float n1 = s1 * at;
            float n2 = s2 * r00 + s3 * r10;
            float n3 = s2 * r01 + s3 * r11;
            ob[t * 32] = C0 * n0 + C1 * n1 + C2 * n2 + C3 * n3;
            s0 = n0; s1 = n1; s2 = n2; s3 = n3;
        }
    }
}

// =======================================================================
extern "C" void kernel_launch(void* const* d_in, const int* in_sizes, int n_in,
                              void* d_out, int out_size) {
    const float* x     = (const float*)d_in[0];
    const float* Wih0  = (const float*)d_in[1];
    const float* Whh0  = (const float*)d_in[2];
    const float* bih0  = (const float*)d_in[3];
    const float* bhh0  = (const float*)d_in[4];
    const float* Wih1  = (const float*)d_in[5];
    const float* Whh1  = (const float*)d_in[6];
    const float* bih1  = (const float*)d_in[7];
    const float* bhh1  = (const float*)d_in[8];
    const float* Wproj = (const float*)d_in[9];
    const float* bproj = (const float*)d_in[10];
    const float* Cm    = (const float*)d_in[11];
    const float* rld   = (const float*)d_in[12];
    const float* rtd   = (const float*)d_in[13];
    const float* rg    = (const float*)d_in[14];
    const float* om    = (const float*)d_in[15];
    float* out = (float*)d_out;

    float *xp0, *xp1, *h1, *hfin;
    cudaGetSymbolAddress((void**)&xp0,  g_xp0);
    cudaGetSymbolAddress((void**)&xp1,  g_xp1);
    cudaGetSymbolAddress((void**)&h1,   g_h1);
    cudaGetSymbolAddress((void**)&hfin, g_hfin);

    cudaFuncSetAttribute(gru_layer<true>,  cudaFuncAttributeMaxDynamicSharedMemorySize, GRU_SMEM_BYTES);
    cudaFuncSetAttribute(gru_layer<false>, cudaFuncAttributeMaxDynamicSharedMemorySize, GRU_SMEM_BYTES);

    const int M = BATCH * SEQ;  // 131072
    dim3 ggrid(G3 / 64, M / 128);

    // Phase 1: layer-0 input projection (K=32)
    gemm_bias<<<ggrid, 256>>>(x, Wih0, bih0, xp0, M, G3, INDIM);
    // Phase 2: layer-0 recurrence, write all h1
    gru_layer<true><<<128, 256, GRU_SMEM_BYTES>>>(xp0, Whh0, bhh0, h1);
    // Phase 3: layer-1 input projection (K=256)
    gemm_bias<<<ggrid, 256>>>(h1, Wih1, bih1, xp1, M, G3, HID);
    // Phase 4: layer-1 recurrence, final h only
    gru_layer<false><<<128, 256, GRU_SMEM_BYTES>>>(xp1, Whh1, bhh1, hfin);
    // Phase 5: projection + decode scan
    final_kernel<<<256, 128>>>(hfin, Wproj, bproj, Cm, rld, rtd, rg, om, out);
}

// round 13
// speedup vs baseline: 1.3434x; 1.3434x over previous
#include <cuda_runtime.h>
#include <cstdint>
#include <math.h>

// Problem dims
#define BATCH 256
#define SEQ   512
#define INDIM 32
#define HID   256
#define G3    768      // 3*HID
#define PREDL 96

// ---------------- scratch (static device memory; no allocation) ----------------
__device__ float g_xp0[(size_t)BATCH * SEQ * G3];   // x @ W_ih_l0^T + b_ih_l0
__device__ float g_xp1[(size_t)BATCH * SEQ * G3];   // h1 @ W_ih_l1^T + b_ih_l1
__device__ float g_h1 [(size_t)BATCH * SEQ * HID];  // layer-0 hidden states
__device__ float g_hfin[BATCH * HID];               // final hidden of layer 1

// ---------------- f32x2 packed helpers ----------------
__device__ __forceinline__ unsigned long long pack2(float lo, float hi) {
    unsigned long long r;
    asm("mov.b64 %0, {%1,%2};" : "=l"(r) : "f"(lo), "f"(hi));
    return r;
}
__device__ __forceinline__ void unpack2(unsigned long long v, float& lo, float& hi) {
    asm("mov.b64 {%0,%1}, %2;" : "=f"(lo), "=f"(hi) : "l"(v));
}
__device__ __forceinline__ unsigned long long ffma2(unsigned long long a,
                                                    unsigned long long b,
                                                    unsigned long long c) {
    unsigned long long d;
    asm("fma.rn.f32x2 %0, %1, %2, %3;" : "=l"(d) : "l"(a), "l"(b), "l"(c));
    return d;
}

__device__ __forceinline__ float fsig(float x) {
    return __fdividef(1.f, 1.f + __expf(-x));
}
__device__ __forceinline__ float ftanh_(float x) {
    return 1.f - __fdividef(2.f, __expf(2.f * x) + 1.f);
}

// =======================================================================
// GEMM v2:  C[M,N] = A[M,K] @ W[N,K]^T + bias[N]   (fp32, FFMA2)
// 128x64 block tile, 8x4 per thread (m-pair FFMA2), 256 threads,
// double-buffered k=16 tiles, one __syncthreads per tile.   (unchanged)
// =======================================================================
__global__ __launch_bounds__(256) void gemm_bias(
        const float* __restrict__ A, const float* __restrict__ W,
        const float* __restrict__ bias, float* __restrict__ C,
        int M, int N, int K) {
    __shared__ float As[2][16][132];
    __shared__ float Bs[2][16][68];
    const int tid = threadIdx.x;
    const int n0 = blockIdx.x * 64;
    const int m0 = blockIdx.y * 128;
    const int tx = tid & 15, ty = tid >> 4;

    const int mA  = tid >> 1;
    const int kcA = (tid & 1) * 2;
    const int nB  = tid >> 2;
    const int kcB = tid & 3;

    const float4* Arow = (const float4*)(A + (size_t)(m0 + mA) * K);
    const float4* Brow = (const float4*)(W + (size_t)(n0 + nB) * K);

    float4 va0 = Arow[kcA];
    float4 va1 = Arow[kcA + 1];
    float4 vb  = Brow[kcB];

    As[0][kcA * 4 + 0][mA] = va0.x; As[0][kcA * 4 + 1][mA] = va0.y;
    As[0][kcA * 4 + 2][mA] = va0.z; As[0][kcA * 4 + 3][mA] = va0.w;
    As[0][kcA * 4 + 4][mA] = va1.x; As[0][kcA * 4 + 5][mA] = va1.y;
    As[0][kcA * 4 + 6][mA] = va1.z; As[0][kcA * 4 + 7][mA] = va1.w;
    Bs[0][kcB * 4 + 0][nB] = vb.x;  Bs[0][kcB * 4 + 1][nB] = vb.y;
    Bs[0][kcB * 4 + 2][nB] = vb.z;  Bs[0][kcB * 4 + 3][nB] = vb.w;
    __syncthreads();

    unsigned long long acc[4][4];
#pragma unroll
    for (int p = 0; p < 4; p++)
#pragma unroll
        for (int n = 0; n < 4; n++) acc[p][n] = 0ull;

    const int ntiles = K >> 4;
    for (int kt = 0; kt < ntiles; kt++) {
        const int s = kt & 1;
        if (kt + 1 < ntiles) {
            va0 = Arow[(kt + 1) * 4 + kcA];
            va1 = Arow[(kt + 1) * 4 + kcA + 1];
            vb  = Brow[(kt + 1) * 4 + kcB];
        }
#pragma unroll
        for (int kk = 0; kk < 16; kk++) {
            const float* ar = &As[s][kk][ty * 8];
            ulonglong2 aA = *(const ulonglong2*)ar;
            ulonglong2 aB = *(const ulonglong2*)(ar + 4);
            float4 b4 = *(const float4*)&Bs[s][kk][tx * 4];
            unsigned long long bp0 = pack2(b4.x, b4.x);
            unsigned long long bp1 = pack2(b4.y, b4.y);
            unsigned long long bp2 = pack2(b4.z, b4.z);
            unsigned long long bp3 = pack2(b4.w, b4.w);
            acc[0][0] = ffma2(aA.x, bp0, acc[0][0]); acc[0][1] = ffma2(aA.x, bp1, acc[0][1]);
            acc[0][2] = ffma2(aA.x, bp2, acc[0][2]); acc[0][3] = ffma2(aA.x, bp3, acc[0][3]);
            acc[1][0] = ffma2(aA.y, bp0, acc[1][0]); acc[1][1] = ffma2(aA.y, bp1, acc[1][1]);
            acc[1][2] = ffma2(aA.y, bp2, acc[1][2]); acc[1][3] = ffma2(aA.y, bp3, acc[1][3]);
            acc[2][0] = ffma2(aB.x, bp0, acc[2][0]); acc[2][1] = ffma2(aB.x, bp1, acc[2][1]);
            acc[2][2] = ffma2(aB.x, bp2, acc[2][2]); acc[2][3] = ffma2(aB.x, bp3, acc[2][3]);
            acc[3][0] = ffma2(aB.y, bp0, acc[3][0]); acc[3][1] = ffma2(aB.y, bp1, acc[3][1]);
            acc[3][2] = ffma2(aB.y, bp2, acc[3][2]); acc[3][3] = ffma2(aB.y, bp3, acc[3][3]);
        }
        if (kt + 1 < ntiles) {
            const int s1 = s ^ 1;
            As[s1][kcA * 4 + 0][mA] = va0.x; As[s1][kcA * 4 + 1][mA] = va0.y;
            As[s1][kcA * 4 + 2][mA] = va0.z; As[s1][kcA * 4 + 3][mA] = va0.w;
            As[s1][kcA * 4 + 4][mA] = va1.x; As[s1][kcA * 4 + 5][mA] = va1.y;
            As[s1][kcA * 4 + 6][mA] = va1.z; As[s1][kcA * 4 + 7][mA] = va1.w;
            Bs[s1][kcB * 4 + 0][nB] = vb.x;  Bs[s1][kcB * 4 + 1][nB] = vb.y;
            Bs[s1][kcB * 4 + 2][nB] = vb.z;  Bs[s1][kcB * 4 + 3][nB] = vb.w;
        }
        __syncthreads();
    }

    float4 bb = *(const float4*)(bias + n0 + tx * 4);
#pragma unroll
    for (int p = 0; p < 4; p++) {
        float l0, h0, l1, h1, l2, h2, l3, h3;
        unpack2(acc[p][0], l0, h0);
        unpack2(acc[p][1], l1, h1);
        unpack2(acc[p][2], l2, h2);
        unpack2(acc[p][3], l3, h3);
        int m = m0 + ty * 8 + p * 2;
        float4 r0 = make_float4(l0 + bb.x, l1 + bb.y, l2 + bb.z, l3 + bb.w);
        float4 r1 = make_float4(h0 + bb.x, h1 + bb.y, h2 + bb.z, h3 + bb.w);
        *(float4*)(C + (size_t)m * N + n0 + tx * 4) = r0;
        *(float4*)(C + (size_t)(m + 1) * N + n0 + tx * 4) = r1;
    }
}

// =======================================================================
// GRU recurrence v6: v3 algorithm + sync (split barrier.cluster), but
// 512 threads/CTA with an 8-way k-split for latency hiding (4 warps/SMSP).
//   keo = tid&7 : k-eighth;  kq = keo>>1, half = keo&1;  u = tid>>3 (0..63)
// Each thread: 3 gates x 8 batch over 32 k, taken as INTERLEAVED 16B chunks
// m = 2c+half of its kq block (bank-slot (2kq+half) mod 8 -> conflict-free
// for both W (68-word rows, unchanged layout) and h (72-word kq stride)).
// Reduce-scatter over the 8 keo lanes (bfly 4,2,1); lane keo finalizes
// batch keo and pushes to all 4 CTAs via DSMEM; split cluster barrier.
// =======================================================================
#define WBLK  13064
#define WT_WORDS (4 * WBLK)             // 52256
#define HSTR  292                       // 4 kq blocks x 72 words + 4 pad
#define HBUF_WORDS (8 * HSTR)           // 2336 per parity buffer
#define GRU_SMEM_FLOATS (WT_WORDS + 2 * HBUF_WORDS)
#define GRU_SMEM_BYTES  (GRU_SMEM_FLOATS * 4)   // 227,712 B

__device__ __forceinline__ uint32_t smem_u32(const void* p) {
    return (uint32_t)__cvta_generic_to_shared(p);
}

template <bool WRITE_ALL>
__global__ __launch_bounds__(512, 1) __cluster_dims__(4, 1, 1)
void gru_layer(const float* __restrict__ xp, const float* __restrict__ W_hh,
               const float* __restrict__ b_hh, float* __restrict__ hout) {
    extern __shared__ float smem[];
    float* Wt   = smem;                 // WT_WORDS
    float* hbuf = smem + WT_WORDS;      // 2 parity buffers

    const int tid  = threadIdx.x;
    const int keo  = tid & 7;
    const int kq   = keo >> 1;
    const int half = keo & 1;
    const int u    = tid >> 3;          // 0..63
    uint32_t rank;
    asm("mov.u32 %0, %%cluster_ctarank;" : "=r"(rank));
    const int gu  = (int)rank * 64 + u;
    const int b0  = (blockIdx.x >> 2) * 8;
    // this lane finalizes batch b0 + keo

    // Load W_hh slice into kq-blocked layout (same as v3, coalesced over k).
    for (int idx = tid; idx < 192 * 256; idx += 512) {
        int row = idx >> 8, k = idx & 255;
        int grow = ((row >> 6) << 8) + (int)rank * 64 + (row & 63);
        Wt[(k >> 6) * WBLK + row * 68 + (k & 63)] = W_hh[grow * 256 + k];
    }
    for (int i = tid; i < 2 * HBUF_WORDS; i += 512) hbuf[i] = 0.f;

    const float bh0 = b_hh[gu], bh1 = b_hh[256 + gu], bh2 = b_hh[512 + gu];

    // running xp pointer for this lane's single batch row
    const float* px = xp + ((size_t)(b0 + keo) * SEQ) * G3 + gu;

    // h[b][k]: phys = b*HSTR + (k>>6)*72 + (k&63).  epilogue offset for
    // (batch keo, unit gu):
    const int hoff_my = keo * HSTR + (int)rank * 72 + u;

    // all CTAs' hbuf init done before anyone pushes / reads
    asm volatile("barrier.cluster.arrive.aligned;" ::: "memory");
    asm volatile("barrier.cluster.wait.aligned;" ::: "memory");

    const bool s4 = (keo & 4), s2 = (keo & 2), s1 = (keo & 1);
    const float* wbase = Wt + kq * WBLK + u * 68 + half * 4;
    const int hb_off = kq * 72 + half * 4;

    for (int t = 0; t < SEQ; t++) {
        const int cur = t & 1, nxt = cur ^ 1;

        // prefetch input projection (hidden under the k-loop)
        float x_r = px[0], x_z = px[256], x_n = px[512];
        px += G3;

        unsigned long long acc[3][8];
#pragma unroll
        for (int g = 0; g < 3; g++)
#pragma unroll
            for (int b = 0; b < 8; b++) acc[g][b] = 0ull;

        const float* hb = hbuf + cur * HBUF_WORDS + hb_off;

        // 8 interleaved chunks: words wbase + 8c (chunk m = 2c+half)
#pragma unroll
        for (int c = 0; c < 8; c++) {
            const int kl = c * 8;
            ulonglong2 w0 = *(const ulonglong2*)(wbase + kl);           // gate r
            ulonglong2 w1 = *(const ulonglong2*)(wbase + 4352 + kl);    // gate z
            ulonglong2 w2 = *(const ulonglong2*)(wbase + 8704 + kl);    // gate n
#pragma unroll
            for (int b = 0; b < 8; b++) {
                ulonglong2 h2 = *(const ulonglong2*)(hb + b * HSTR + kl);
                acc[0][b] = ffma2(w0.x, h2.x, acc[0][b]);
                acc[0][b] = ffma2(w0.y, h2.y, acc[0][b]);
                acc[1][b] = ffma2(w1.x, h2.x, acc[1][b]);
                acc[1][b] = ffma2(w1.y, h2.y, acc[1][b]);
                acc[2][b] = ffma2(w2.x, h2.x, acc[2][b]);
                acc[2][b] = ffma2(w2.y, h2.y, acc[2][b]);
            }
        }

        // previous h for this lane's batch
        float hp = hbuf[cur * HBUF_WORDS + hoff_my];

        // k-parity collapse
        float v[3][8];
#pragma unroll
        for (int g = 0; g < 3; g++)
#pragma unroll
            for (int b = 0; b < 8; b++) {
                float lo, hi;
                unpack2(acc[g][b], lo, hi);
                v[g][b] = lo + hi;
            }

        // reduce-scatter over the 8 keo lanes; lane keo keeps batch keo.
        // stage xor4: keep batches {0..3} if !s4 else {4..7}  (12 shfl)
        float v4[3][4];
#pragma unroll
        for (int g = 0; g < 3; g++)
#pragma unroll
            for (int j = 0; j < 4; j++) {
                float send = s4 ? v[g][j] : v[g][j + 4];
                float keep = s4 ? v[g][j + 4] : v[g][j];
                v4[g][j] = keep + __shfl_xor_sync(0xFFFFFFFFu, send, 4);
            }
        // stage xor2: keep {0,1} if !s2 else {2,3}  (6 shfl)
        float v2[3][2];
#pragma unroll
        for (int g = 0; g < 3; g++)
#pragma unroll
            for (int j = 0; j < 2; j++) {
                float send = s2 ? v4[g][j] : v4[g][j + 2];
                float keep = s2 ? v4[g][j + 2] : v4[g][j];
                v2[g][j] = keep + __shfl_xor_sync(0xFFFFFFFFu, send, 2);
            }
        // stage xor1: keep one  (3 shfl)
        float s[3];
#pragma unroll
        for (int g = 0; g < 3; g++) {
            float send = s1 ? v2[g][0] : v2[g][1];
            float keep = s1 ? v2[g][1] : v2[g][0];
            s[g] = keep + __shfl_xor_sync(0xFFFFFFFFu, send, 1);
        }

        float r = fsig(x_r + s[0] + bh0);
        float z = fsig(x_z + s[1] + bh1);
        float n = ftanh_(x_n + r * (s[2] + bh2));
        float hn = (1.f - z) * n + z * hp;

        // push this batch to all 4 CTAs' next buffer
        uint32_t laddr = smem_u32(hbuf + nxt * HBUF_WORDS + hoff_my);
#pragma unroll
        for (int p = 0; p < 4; p++) {
            uint32_t ra;
            asm volatile("mapa.shared::cluster.u32 %0, %1, %2;"
                         : "=r"(ra) : "r"(laddr), "r"(p));
            asm volatile("st.shared::cluster.f32 [%0], %1;"
                         :: "r"(ra), "f"(hn) : "memory");
        }

        asm volatile("barrier.cluster.arrive.aligned;" ::: "memory");

        // global h write overlaps the barrier
        if (WRITE_ALL)
            hout[((size_t)(b0 + keo) * SEQ + t) * HID + gu] = hn;
        else if (t == SEQ - 1)
            hout[(b0 + keo) * HID + gu] = hn;

        asm volatile("barrier.cluster.wait.aligned;" ::: "memory");
    }
}

// =======================================================================
// Final projection + 96-step linear state-space decode. 1 block per batch row.
// =======================================================================
__global__ void final_kernel(const float* __restrict__ hfin, const float* __restrict__ Wp,
                             const float* __restrict__ bp, const float* __restrict__ Cm,
                             const float* __restrict__ rld, const float* __restrict__ rtd,
                             const float* __restrict__ rg, const float* __restrict__ om,
                             float* __restrict__ out) {
    __shared__ float hs[256];
    __shared__ float ss[128];
    const int b = blockIdx.x, tid = threadIdx.x;  // 128 threads
    hs[tid]       = hfin[b * 256 + tid];
    hs[tid + 128] = hfin[b * 256 + 128 + tid];
    __syncthreads();

    float acc = bp[tid];
    const float* w = Wp + tid * 256;
#pragma unroll 8
    for (int k = 0; k < 256; k++) acc += w[k] * hs[k];
    ss[tid] = acc;
    __syncthreads();

    if (tid < 32) {
        const int d = tid;
        float s0 = ss[d * 4 + 0], s1 = ss[d * 4 + 1], s2 = ss[d * 4 + 2], s3 = ss[d * 4 + 3];
        const float al = 1.f / (1.f + expf(-rld[d])) * 0.15f + 0.85f;
        const float at = 1.f / (1.f + expf(-rtd[d])) * 0.25f + 0.70f;
        const float g  = 1.f / (1.f + expf(-rg[d]))  * 0.20f + 0.80f;
        const float c = cosf(om[d]), sn = sinf(om[d]);
        const float r00 = g * c, r01 = -g * sn, r10 = g * sn, r11 = g * c;
        const float C0 = Cm[d * 4 + 0], C1 = Cm[d * 4 + 1];
        const float C2 = Cm[d * 4 + 2], C3 = Cm[d * 4 + 3];
        float* ob = out + (size_t)b * PREDL * 32 + d;
#pragma unroll 4
        for (int t = 0; t < PREDL; t++) {
            float n0 = s0 * al;
            float n1 = s1 * at;
            float n2 = s2 * r00 + s3 * r10;
            float n3 = s2 * r01 + s3 * r11;
            ob[t * 32] = C0 * n0 + C1 * n1 + C2 * n2 + C3 * n3;
            s0 = n0; s1 = n1; s2 = n2; s3 = n3;
        }
    }
}

// =======================================================================
extern "C" void kernel_launch(void* const* d_in, const int* in_sizes, int n_in,
                              void* d_out, int out_size) {
    const float* x     = (const float*)d_in[0];
    const float* Wih0  = (const float*)d_in[1];
    const float* Whh0  = (const float*)d_in[2];
    const float* bih0  = (const float*)d_in[3];
    const float* bhh0  = (const float*)d_in[4];
    const float* Wih1  = (const float*)d_in[5];
    const float* Whh1  = (const float*)d_in[6];
    const float* bih1  = (const float*)d_in[7];
    const float* bhh1  = (const float*)d_in[8];
    const float* Wproj = (const float*)d_in[9];
    const float* bproj = (const float*)d_in[10];
    const float* Cm    = (const float*)d_in[11];
    const float* rld   = (const float*)d_in[12];
    const float* rtd   = (const float*)d_in[13];
    const float* rg    = (const float*)d_in[14];
    const float* om    = (const float*)d_in[15];
    float* out = (float*)d_out;

    float *xp0, *xp1, *h1, *hfin;
    cudaGetSymbolAddress((void**)&xp0,  g_xp0);
    cudaGetSymbolAddress((void**)&xp1,  g_xp1);
    cudaGetSymbolAddress((void**)&h1,   g_h1);
    cudaGetSymbolAddress((void**)&hfin, g_hfin);

    cudaFuncSetAttribute(gru_layer<true>,  cudaFuncAttributeMaxDynamicSharedMemorySize, GRU_SMEM_BYTES);
    cudaFuncSetAttribute(gru_layer<false>, cudaFuncAttributeMaxDynamicSharedMemorySize, GRU_SMEM_BYTES);

    const int M = BATCH * SEQ;  // 131072
    dim3 ggrid(G3 / 64, M / 128);

    // Phase 1: layer-0 input projection (K=32)
    gemm_bias<<<ggrid, 256>>>(x, Wih0, bih0, xp0, M, G3, INDIM);
    // Phase 2: layer-0 recurrence, write all h1
    gru_layer<true><<<128, 512, GRU_SMEM_BYTES>>>(xp0, Whh0, bhh0, h1);
    // Phase 3: layer-1 input projection (K=256)
    gemm_bias<<<ggrid, 256>>>(h1, Wih1, bih1, xp1, M, G3, HID);
    // Phase 4: layer-1 recurrence, final h only
    gru_layer<false><<<128, 512, GRU_SMEM_BYTES>>>(xp1, Whh1, bhh1, hfin);
    // Phase 5: projection + decode scan
    final_kernel<<<256, 128>>>(hfin, Wproj, bproj, Cm, rld, rtd, rg, om, out);
}